// round 16
// baseline (speedup 1.0000x reference)
#include <cuda_runtime.h>
#include <cuda_bf16.h>
#include <cstdint>

#define HH 224
#define WW 224
#define HW (HH*WW)
#define OH 448
#define OW 448
#define OHW (OH*OW)

typedef unsigned int u32;
typedef unsigned long long u64;

// ---------------------------------------------------------------------------
// Scratch: activations pixel-major packed (bf16 hi | bf16 lo<<16)
// ---------------------------------------------------------------------------
__device__ u32  act2_x0[HW * 100];
__device__ u32  act2_feats[5 * HW * 100];
__device__ float g_x36[36 * HW];
__device__ float g_smn[2 * HW];
// K-packed weight images per layer:
//   8 full stages: [112 oc][120-halves stride, 112 k used] hi then lo
//   1 tail stage:  [112 oc][16-halves stride (32 B, ldsm-aligned)] hi then lo
#define LAYER_HALVES (8 * 26880 + 3584)
__device__ __align__(16) __nv_bfloat16 g_wimg[5 * LAYER_HALVES];

// ---------------------------------------------------------------------------
// helpers
// ---------------------------------------------------------------------------
__device__ __forceinline__ u32 smem_u32(const void* p) {
    u32 r;
    asm("{ .reg .u64 t; cvta.to.shared.u64 t, %1; cvt.u32.u64 %0, t; }"
        : "=r"(r) : "l"(p));
    return r;
}
__device__ __forceinline__ void cp16(u32 dst, const void* src) {
    asm volatile("cp.async.cg.shared.global [%0], [%1], 16;"
                 :: "r"(dst), "l"(src));
}
__device__ __forceinline__ void cp_commit() { asm volatile("cp.async.commit_group;"); }
template <int N>
__device__ __forceinline__ void cp_waitN() {
    asm volatile("cp.async.wait_group %0;" :: "n"(N));
}

__device__ __forceinline__ void ldsm4(u32* r, u32 addr) {
    asm volatile("ldmatrix.sync.aligned.m8n8.x4.shared.b16 {%0,%1,%2,%3}, [%4];"
        : "=r"(r[0]), "=r"(r[1]), "=r"(r[2]), "=r"(r[3]) : "r"(addr));
}
__device__ __forceinline__ void mma16816(float* c, const u32* a, u32 b0, u32 b1) {
    asm volatile("mma.sync.aligned.m16n8k16.row.col.f32.bf16.bf16.f32 "
        "{%0,%1,%2,%3}, {%4,%5,%6,%7}, {%8,%9}, {%0,%1,%2,%3};"
        : "+f"(c[0]), "+f"(c[1]), "+f"(c[2]), "+f"(c[3])
        : "r"(a[0]), "r"(a[1]), "r"(a[2]), "r"(a[3]), "r"(b0), "r"(b1));
}

// pack/unpack fp32 <-> (bf16 hi in low16 | bf16 lo in high16)
__device__ __forceinline__ u32 pack_hl(float v) {
    __nv_bfloat16 h = __float2bfloat16(v);
    float fh = __bfloat162float(h);
    __nv_bfloat16 l = __float2bfloat16(v - fh);
    return (u32)__bfloat16_as_ushort(h) | ((u32)__bfloat16_as_ushort(l) << 16);
}
__device__ __forceinline__ float unpack_hl(u32 b) {
    return __uint_as_float(b << 16) + __uint_as_float(b & 0xFFFF0000u);
}

// f32x2
__device__ __forceinline__ u64 pack2f(float lo, float hi) {
    u64 r; asm("mov.b64 %0, {%1, %2};" : "=l"(r) : "f"(lo), "f"(hi)); return r;
}
__device__ __forceinline__ void unpack2f(u64 v, float& lo, float& hi) {
    asm("mov.b64 {%0, %1}, %2;" : "=f"(lo), "=f"(hi) : "l"(v));
}
__device__ __forceinline__ void ffma2(u64& acc, u64 a, u64 b) {
    asm("fma.rn.f32x2 %0, %1, %2, %0;" : "+l"(acc) : "l"(a), "l"(b));
}

// ---------------------------------------------------------------------------
// Prep: K-packed weight images. grid = 45 (layer*9 + stage)
// ---------------------------------------------------------------------------
__global__ __launch_bounds__(256) void prep_weights_kernel(
    const float* __restrict__ w_head, const float* __restrict__ w_blocks)
{
    int l = blockIdx.x / 9, s = blockIdx.x - 9 * (blockIdx.x / 9);
    const float* src = (l == 0) ? w_head : (w_blocks + (l - 1) * 90000);
    int stride = (s < 8) ? 120 : 16;
    int nk = (s < 8) ? 112 : 16;
    int splitsz = 112 * stride;
    __nv_bfloat16* dhi = g_wimg + (size_t)l * LAYER_HALVES + s * 26880;
    __nv_bfloat16* dlo = dhi + splitsz;
    int total = 112 * stride;
    for (int i = threadIdx.x; i < total; i += 256) {
        int oc = i / stride, kk = i - stride * (i / stride);
        int k = s * 112 + kk;
        float wv = 0.f;
        if (oc < 100 && kk < nk && k < 900) {
            int kp = k / 100, ci = k - kp * 100;
            wv = src[oc * 900 + ci * 9 + kp];
        }
        __nv_bfloat16 h = __float2bfloat16(wv);
        __nv_bfloat16 lo = __float2bfloat16(wv - __bfloat162float(h));
        dhi[i] = h;
        dlo[i] = lo;
    }
}

// ---------------------------------------------------------------------------
// Kernel 1: warp + concat -> act2_x0 [p][100], smem-buffered coalesced writes
// ---------------------------------------------------------------------------
#define WC_SMEM (256 * 100 * 4)

__global__ __launch_bounds__(256) void warp_concat_kernel(
    const float* __restrict__ f0, const float* __restrict__ f1,
    const float* __restrict__ fd, const float* __restrict__ flow)
{
    extern __shared__ u32 s_out[];   // [256 px][100 ch]
    const int tid = threadIdx.x;
    const int pixbase = blockIdx.x * 256;
    const int p = pixbase + tid;
    u32* row = s_out + tid * 100;

    int y = p / WW, x = p - y * WW;

    #pragma unroll 4
    for (int c = 0; c < 32; c++) row[64 + c] = pack_hl(fd[c * HW + p]);
    #pragma unroll
    for (int c = 0; c < 4; c++)  row[96 + c] = pack_hl(flow[c * HW + p]);

    #pragma unroll
    for (int pair = 0; pair < 2; pair++) {
        const float* img = (pair == 0) ? f0 : f1;
        float px = (float)x + flow[(pair * 2 + 0) * HW + p];
        float py = (float)y + flow[(pair * 2 + 1) * HW + p];
        float fx = floorf(px), fy = floorf(py);
        float wx = px - fx, wy = py - fy;
        int ix = (int)fminf(fmaxf(fx, -2.f), 226.f);
        int iy = (int)fminf(fmaxf(fy, -2.f), 226.f);
        int x0i = min(max(ix, 0), WW - 1);
        int x1i = min(max(ix + 1, 0), WW - 1);
        int y0i = min(max(iy, 0), HH - 1);
        int y1i = min(max(iy + 1, 0), HH - 1);
        float w00 = (1.f - wx) * (1.f - wy);
        float w01 = wx * (1.f - wy);
        float w10 = (1.f - wx) * wy;
        float w11 = wx * wy;
        int b00 = y0i * WW + x0i, b01 = y0i * WW + x1i;
        int b10 = y1i * WW + x0i, b11 = y1i * WW + x1i;
        #pragma unroll 4
        for (int c = 0; c < 32; c++) {
            const float* g = img + c * HW;
            float v = g[b00] * w00 + g[b01] * w01 + g[b10] * w10 + g[b11] * w11;
            row[pair * 32 + c] = pack_hl(v);
        }
    }
    __syncthreads();

    u32* dst = act2_x0 + (size_t)pixbase * 100;
    for (int i = tid; i < 25600; i += 256) dst[i] = s_out[i];
}

// ---------------------------------------------------------------------------
// Kernel 2: HMMA implicit-GEMM 3x3 conv, K-packed (K = 912, 57 ksteps),
// B-fragment prefetch depth 2 (triple-buffered).
// CTA: 128 px x 112 oc. 8 warps, each full-M (7 m-tiles) x 16 px (2 nf).
// 4-slot weight ring, prefetch distance 2, single barrier/stage.
// Split bf16 hi/lo, 3 products, fp32 accum.
// ---------------------------------------------------------------------------
#define WSTRIDE 240       // smem row stride bytes (full stages)
#define SPLIT_B 26880     // hi->lo offset within full stage
#define SLOT_B  53760     // full stage bytes (ring slot size)
#define CONV_DSMEM (4 * SLOT_B)   // 215040 B
#define TAIL_SPLIT 3584   // hi->lo offset in tail stage

__device__ __forceinline__ void loadB2K(u32* b, int k16, int cib, int kb,
    const u32* rA0, const u32* rA1, bool oA0, bool oA1,
    const u32* rB0, const u32* rB1, bool oB0, bool oB1)
{
    #pragma unroll
    for (int nf = 0; nf < 2; nf++) {
        const u32* rA = nf ? rA1 : rA0; bool oA = nf ? oA1 : oA0;
        const u32* rB = nf ? rB1 : rB0; bool oB = nf ? oB1 : oB0;
        u32 v0 = 0, v1 = 0, w0 = 0, w1 = 0;
        int kv = k16 + cib;
        {
            bool ub = kv >= kb;
            const u32* r = ub ? rB : rA;
            bool ok = ub ? oB : oA;
            int ci = kv - (ub ? kb : kb - 100);
            if (ok) { uint2 t = *(const uint2*)(r + ci); v0 = t.x; v1 = t.y; }
        }
        kv += 8;
        {
            bool ub = kv >= kb;
            const u32* r = ub ? rB : rA;
            bool ok = ub ? oB : oA;
            int ci = kv - (ub ? kb : kb - 100);
            if (ok) { uint2 t = *(const uint2*)(r + ci); w0 = t.x; w1 = t.y; }
        }
        b[nf * 4 + 0] = __byte_perm(v0, v1, 0x5410);  // hi pair k,k+1
        b[nf * 4 + 1] = __byte_perm(w0, w1, 0x5410);  // hi pair k+8,k+9
        b[nf * 4 + 2] = __byte_perm(v0, v1, 0x7632);  // lo pair
        b[nf * 4 + 3] = __byte_perm(w0, w1, 0x7632);
    }
}

template <int MODE>
__global__ __launch_bounds__(256, 1) void conv_hmma_kernel(
    const u32* __restrict__ in,                 // [HW][100]
    const __nv_bfloat16* __restrict__ wimg,     // layer base (halves)
    const float* __restrict__ aux,
    const float* __restrict__ mask,
    u32* __restrict__ outp)                     // [HW][100]
{
    extern __shared__ __align__(16) char dsm[];
    __shared__ float s_mask[128];
    __shared__ float s_aux[112];

    const int tid = threadIdx.x;
    const int w = tid >> 5;
    const int lid = tid & 31;
    const int pixbase = blockIdx.x << 7;

    if (tid < 128) s_mask[tid] = mask[pixbase + tid];
    if (tid < 112) s_aux[tid] = (tid < 100) ? aux[tid] : 0.f;

    const u32 sb = smem_u32(dsm);

    const int p0 = pixbase + w * 16 + (lid >> 2);
    const int p1 = p0 + 8;
    const int py0 = p0 / WW, px0 = p0 - py0 * WW;
    const int py1 = p1 / WW, px1 = p1 - py1 * WW;

    float acc[7][2][4];
    #pragma unroll
    for (int m = 0; m < 7; m++)
        #pragma unroll
        for (int nf = 0; nf < 2; nf++)
            #pragma unroll
            for (int i = 0; i < 4; i++) acc[m][nf][i] = 0.f;

    auto stageW = [&](int s) {
        const char* src = (const char*)wimg + (size_t)s * SLOT_B;
        u32 dst = sb + (s & 3) * SLOT_B;
        int chunks = (s < 8) ? 3360 : 448;
        for (int i = tid; i < chunks; i += 256) cp16(dst + i * 16, src + i * 16);
        cp_commit();
    };

    stageW(0);
    stageW(1);

    const int cib = (lid & 3) * 2;
    const u32 arow = (lid & 15) * WSTRIDE + (lid >> 4) * 16;

    auto rowsFor = [&](int kp, const u32*& r0, const u32*& r1,
                       bool& ok0, bool& ok1) {
        int ky = kp / 3 - 1, kx = kp - 3 * (kp / 3) - 1;
        int iy0 = py0 + ky, ix0 = px0 + kx;
        int iy1 = py1 + ky, ix1 = px1 + kx;
        ok0 = (iy0 >= 0) & (iy0 < HH) & (ix0 >= 0) & (ix0 < WW);
        ok1 = (iy1 >= 0) & (iy1 < HH) & (ix1 >= 0) & (ix1 < WW);
        r0 = in + (size_t)(iy0 * WW + ix0) * 100;
        r1 = in + (size_t)(iy1 * WW + ix1) * 100;
    };

    // A-side = kpos s, B-side = kpos s+1 for stage s
    const u32 *rA0, *rA1, *rB0, *rB1, *rN0, *rN1;
    bool oA0, oA1, oB0, oB1, oN0, oN1;
    rowsFor(0, rA0, rA1, oA0, oA1);
    rowsFor(1, rB0, rB1, oB0, oB1);

    // triple-buffered B fragments: bc = current kstep, b1 = +1, b2 = +2
    u32 bc[8], b1[8], b2[8];
    loadB2K(bc, 0,  cib, 100, rA0, rA1, oA0, oA1, rB0, rB1, oB0, oB1);
    loadB2K(b1, 16, cib, 100, rA0, rA1, oA0, oA1, rB0, rB1, oB0, oB1);

    for (int s = 0; s < 8; s++) {
        if (s + 2 <= 8) stageW(s + 2);
        if (s <= 6) cp_waitN<2>();
        else        cp_waitN<1>();
        __syncthreads();   // single barrier per stage

        const u32 sbuf = sb + (s & 3) * SLOT_B;
        const int kb = (s + 1) * 100;

        if (s < 7) rowsFor(s + 2, rN0, rN1, oN0, oN1);
        else { rN0 = rB0; rN1 = rB1; oN0 = false; oN1 = false; }

        #pragma unroll
        for (int ks = 0; ks < 7; ks++) {
            // prefetch kstep (s*7 + ks + 2); uniform k16 works across
            // the stage boundary: next-stage kstep ks2 = ks+2-7 has
            // 112(s+1)+16*ks2 == 112s+16(ks+2).
            if (ks < 5) {
                loadB2K(b2, s * 112 + (ks + 2) * 16, cib, kb,
                        rA0, rA1, oA0, oA1, rB0, rB1, oB0, oB1);
            } else if (s * 7 + ks + 2 <= 56) {
                loadB2K(b2, s * 112 + (ks + 2) * 16, cib, kb + 100,
                        rB0, rB1, oB0, oB1, rN0, rN1, oN0, oN1);
            }

            const u32 kaddr = sbuf + arow + ks * 32;
            #pragma unroll
            for (int m = 0; m < 7; m++) {
                u32 ah[4], al[4];
                ldsm4(ah, kaddr + m * 3840);
                ldsm4(al, kaddr + m * 3840 + SPLIT_B);
                #pragma unroll
                for (int nf = 0; nf < 2; nf++) {
                    mma16816(acc[m][nf], ah, bc[nf * 4 + 0], bc[nf * 4 + 1]); // hh
                    mma16816(acc[m][nf], ah, bc[nf * 4 + 2], bc[nf * 4 + 3]); // h*l
                    mma16816(acc[m][nf], al, bc[nf * 4 + 0], bc[nf * 4 + 1]); // l*h
                }
            }
            #pragma unroll
            for (int q = 0; q < 8; q++) { bc[q] = b1[q]; b1[q] = b2[q]; }
        }
        // rotate kpos pointers
        rA0 = rB0; rA1 = rB1; oA0 = oB0; oA1 = oB1;
        rB0 = rN0; rB1 = rN1; oB0 = oN0; oB1 = oN1;
    }

    // tail stage (s=8, slot 0, 1 kstep, row stride 32 B) — uses bc
    {
        cp_waitN<0>();
        __syncthreads();
        const u32 sbuf = sb + 0 * SLOT_B;
        const u32 kaddr = sbuf + (lid & 15) * 32 + (lid >> 4) * 16;
        #pragma unroll
        for (int m = 0; m < 7; m++) {
            u32 ah[4], al[4];
            ldsm4(ah, kaddr + m * 512);
            ldsm4(al, kaddr + m * 512 + TAIL_SPLIT);
            #pragma unroll
            for (int nf = 0; nf < 2; nf++) {
                mma16816(acc[m][nf], ah, bc[nf * 4 + 0], bc[nf * 4 + 1]);
                mma16816(acc[m][nf], ah, bc[nf * 4 + 2], bc[nf * 4 + 3]);
                mma16816(acc[m][nf], al, bc[nf * 4 + 0], bc[nf * 4 + 1]);
            }
        }
    }
    __syncthreads();   // protect dsm reuse by epilogue

    // epilogue: transform + smem transpose + coalesced store
    u32* tr = (u32*)dsm;      // [128 px][stride 116] u32
    #pragma unroll
    for (int m = 0; m < 7; m++) {
        const int oc0 = m * 16 + (lid >> 2);
        #pragma unroll
        for (int nf = 0; nf < 2; nf++) {
            const int pxc = w * 16 + nf * 8 + (lid & 3) * 2;
            #pragma unroll
            for (int i = 0; i < 4; i++) {
                const int oc = oc0 + (i >> 1) * 8;
                const int px = pxc + (i & 1);
                if (oc < 100) {
                    float v = acc[m][nf][i];
                    float a = s_aux[oc], mm = s_mask[px];
                    if (MODE == 0) {
                        v = (v >= 0.f ? v : a * v) * mm;
                    } else {
                        v *= mm;
                        v = (v >= 0.f ? v : a * v);
                    }
                    tr[px * 116 + oc] = pack_hl(v);
                }
            }
        }
    }
    __syncthreads();
    for (int i = tid; i < 12800; i += 256) {
        int px = i / 100, ci = i - 100 * (i / 100);
        outp[(size_t)(pixbase + px) * 100 + ci] = tr[px * 116 + ci];
    }
}

// ---------------------------------------------------------------------------
// Kernel 3: 1x1 conv 500 -> 36, f32x2, smem-tiled coalesced reads
// ---------------------------------------------------------------------------
#define C1_SMEM (128 * 101 * 4 + 3600 * 4)

__global__ __launch_bounds__(256) void conv1x1_kernel(
    const u32* __restrict__ feats, const float* __restrict__ wl,
    const float* __restrict__ bl, float* __restrict__ out)
{
    extern __shared__ __align__(16) char c1sm[];
    u32* s_f = (u32*)c1sm;                       // [128 px][101]
    float* s_w = (float*)(c1sm + 128 * 101 * 4);

    const int tid = threadIdx.x;
    const int px = tid & 127;
    const int half = tid >> 7;
    const int prb = half * 9;
    const size_t p = (size_t)blockIdx.x * 128 + px;

    u64 acc[9];
    #pragma unroll
    for (int pr = 0; pr < 9; pr++)
        acc[pr] = pack2f(bl[(prb + pr) * 2], bl[(prb + pr) * 2 + 1]);

    for (int ch = 0; ch < 5; ch++) {
        __syncthreads();
        for (int i = tid; i < 3600; i += 256) {
            int ci = i / 36, o = i - ci * 36;
            s_w[(ci * 18 + (o >> 1)) * 2 + (o & 1)] = wl[o * 500 + ch * 100 + ci];
        }
        const u32* src = feats + ((size_t)ch * HW + (size_t)blockIdx.x * 128) * 100;
        for (int i = tid; i < 12800; i += 256) {
            int lpx = i / 100, lci = i - 100 * (i / 100);
            s_f[lpx * 101 + lci] = src[i];
        }
        __syncthreads();

        const u32* fp = s_f + px * 101;
        #pragma unroll 4
        for (int ci = 0; ci < 100; ci++) {
            float f = unpack_hl(fp[ci]);
            u64 f2 = pack2f(f, f);
            const u64* wp = (const u64*)(s_w + ci * 36) + prb;
            #pragma unroll
            for (int pr = 0; pr < 9; pr++) ffma2(acc[pr], wp[pr], f2);
        }
    }
    #pragma unroll
    for (int pr = 0; pr < 9; pr++) {
        float v0, v1;
        unpack2f(acc[pr], v0, v1);
        out[((prb + pr) * 2 + 0) * HW + p] = v0;
        out[((prb + pr) * 2 + 1) * HW + p] = v1;
    }
}

// ---------------------------------------------------------------------------
// Kernel 2b: small 3x3 conv (mask head), 32 -> 2, bias
// ---------------------------------------------------------------------------
__global__ __launch_bounds__(256) void conv3x3_small_kernel(
    const float* __restrict__ in, const float* __restrict__ wgt,
    const float* __restrict__ bias, float* __restrict__ out)
{
    __shared__ float s_in[10 * 34];
    __shared__ float s_w[2 * 9];

    const int tid = threadIdx.x;
    const int tx = tid & 31;
    const int ty = tid >> 5;
    const int ox0 = blockIdx.x * 32;
    const int oy0 = blockIdx.y * 8;
    const int ox = ox0 + tx, oy = oy0 + ty;

    float acc0 = 0.f, acc1 = 0.f;

    for (int ci = 0; ci < 32; ci++) {
        #pragma unroll
        for (int idx = tid; idx < 340; idx += 256) {
            int r = idx / 34, c = idx - r * 34;
            int gy = oy0 - 1 + r, gx = ox0 - 1 + c;
            float v = 0.f;
            if (gx >= 0 && gx < WW && gy >= 0 && gy < HH)
                v = in[ci * HW + gy * WW + gx];
            s_in[idx] = v;
        }
        if (tid < 18)
            s_w[tid] = wgt[(tid / 9) * (32 * 9) + ci * 9 + (tid % 9)];
        __syncthreads();

        float r[9];
        #pragma unroll
        for (int ky = 0; ky < 3; ky++)
            #pragma unroll
            for (int kx = 0; kx < 3; kx++)
                r[ky * 3 + kx] = s_in[(ty + ky) * 34 + tx + kx];

        #pragma unroll
        for (int k = 0; k < 9; k++) {
            acc0 = fmaf(s_w[k], r[k], acc0);
            acc1 = fmaf(s_w[9 + k], r[k], acc1);
        }
        __syncthreads();
    }
    out[oy * WW + ox] = acc0 + bias[0];
    out[HW + oy * WW + ox] = acc1 + bias[1];
}

// ---------------------------------------------------------------------------
// Kernel 4: 2x bilinear upsample + mask
// ---------------------------------------------------------------------------
__global__ __launch_bounds__(256) void upsample_kernel(
    const float* __restrict__ x36, const float* __restrict__ smn,
    const float* __restrict__ smask, float* __restrict__ out)
{
    int p = blockIdx.x * 256 + threadIdx.x;
    if (p >= OHW) return;
    int oy = p / OW, ox = p - oy * OW;
    int iy = oy >> 1, ix = ox >> 1;

    int r0, r1; float wr0, wr1;
    if (oy & 1) { r0 = iy; r1 = min(iy + 1, HH - 1); wr0 = 0.75f; wr1 = 0.25f; }
    else        { r0 = max(iy - 1, 0); r1 = iy;      wr0 = 0.25f; wr1 = 0.75f; }
    int c0, c1; float wc0, wc1;
    if (ox & 1) { c0 = ix; c1 = min(ix + 1, WW - 1); wc0 = 0.75f; wc1 = 0.25f; }
    else        { c0 = max(ix - 1, 0); c1 = ix;      wc0 = 0.25f; wc1 = 0.75f; }

    int b00 = r0 * WW + c0, b01 = r0 * WW + c1;
    int b10 = r1 * WW + c0, b11 = r1 * WW + c1;

    #pragma unroll 4
    for (int ch = 0; ch < 36; ch++) {
        const float* g = x36 + ch * HW;
        float v = wr0 * (wc0 * g[b00] + wc1 * g[b01]) +
                  wr1 * (wc0 * g[b10] + wc1 * g[b11]);
        out[ch * OHW + p] = v;
    }

    const float* s0p = smn;
    const float* s1p = smn + HW;
    float s0 = wr0 * (wc0 * s0p[b00] + wc1 * s0p[b01]) +
               wr1 * (wc0 * s0p[b10] + wc1 * s0p[b11]);
    float s1 = wr0 * (wc0 * s1p[b00] + wc1 * s1p[b01]) +
               wr1 * (wc0 * s1p[b10] + wc1 * s1p[b11]);
    float mu = smask[iy * WW + ix];
    out[36 * OHW + p] = (s0 > s1) ? mu : 0.f;
}

// ---------------------------------------------------------------------------
// Launcher
// ---------------------------------------------------------------------------
extern "C" void kernel_launch(void* const* d_in, const int* in_sizes, int n_in,
                              void* d_out, int out_size)
{
    const float* feat_0     = (const float*)d_in[0];
    const float* feat_1     = (const float*)d_in[1];
    const float* feat_dense = (const float*)d_in[2];
    const float* flow       = (const float*)d_in[3];
    const float* space_mask = (const float*)d_in[4];
    const float* w_head     = (const float*)d_in[5];
    const float* a_head     = (const float*)d_in[6];
    const float* w_blocks   = (const float*)d_in[7];
    const float* a_blocks   = (const float*)d_in[8];
    const float* w_last     = (const float*)d_in[9];
    const float* b_last     = (const float*)d_in[10];
    const float* w_mask     = (const float*)d_in[11];
    const float* b_mask     = (const float*)d_in[12];

    u32 *x0a, *featsa;
    float *x36, *smn;
    __nv_bfloat16* wimg;
    cudaGetSymbolAddress((void**)&x0a,    act2_x0);
    cudaGetSymbolAddress((void**)&featsa, act2_feats);
    cudaGetSymbolAddress((void**)&x36,    g_x36);
    cudaGetSymbolAddress((void**)&smn,    g_smn);
    cudaGetSymbolAddress((void**)&wimg,   g_wimg);

    cudaFuncSetAttribute(conv_hmma_kernel<0>,
                         cudaFuncAttributeMaxDynamicSharedMemorySize, CONV_DSMEM);
    cudaFuncSetAttribute(conv_hmma_kernel<1>,
                         cudaFuncAttributeMaxDynamicSharedMemorySize, CONV_DSMEM);
    cudaFuncSetAttribute(warp_concat_kernel,
                         cudaFuncAttributeMaxDynamicSharedMemorySize, WC_SMEM);
    cudaFuncSetAttribute(conv1x1_kernel,
                         cudaFuncAttributeMaxDynamicSharedMemorySize, C1_SMEM);

    prep_weights_kernel<<<45, 256>>>(w_head, w_blocks);
    warp_concat_kernel<<<196, 256, WC_SMEM>>>(feat_0, feat_1, feat_dense, flow);

    conv_hmma_kernel<0><<<392, 256, CONV_DSMEM>>>(
        x0a, wimg, a_head, space_mask, featsa);
    for (int i = 1; i < 5; i++) {
        conv_hmma_kernel<1><<<392, 256, CONV_DSMEM>>>(
            featsa + (size_t)(i - 1) * HW * 100,
            wimg + (size_t)i * LAYER_HALVES,
            a_blocks + (i - 1) * 100,
            space_mask,
            featsa + (size_t)i * HW * 100);
    }

    conv1x1_kernel<<<392, 256, C1_SMEM>>>(featsa, w_last, b_last, x36);

    conv3x3_small_kernel<<<dim3(7, 28, 1), 256>>>(
        x36 + 4 * HW, w_mask, b_mask, smn);

    upsample_kernel<<<784, 256>>>(x36, smn, space_mask, (float*)d_out);
}

// round 17
// speedup vs baseline: 1.0258x; 1.0258x over previous
#include <cuda_runtime.h>
#include <cuda_bf16.h>
#include <cstdint>

#define HH 224
#define WW 224
#define HW (HH*WW)
#define OH 448
#define OW 448
#define OHW (OH*OW)

typedef unsigned int u32;
typedef unsigned long long u64;

// ---------------------------------------------------------------------------
// Scratch: activations pixel-major packed (bf16 hi | bf16 lo<<16)
// ---------------------------------------------------------------------------
__device__ u32  act2_x0[HW * 100];
__device__ u32  act2_feats[5 * HW * 100];
__device__ float g_x36[36 * HW];
__device__ float g_smn[2 * HW];
// K-packed weight images per layer:
//   8 full stages: [112 oc][120-halves stride, 112 k used] hi then lo
//   1 tail stage:  [112 oc][16-halves stride (32 B, ldsm-aligned)] hi then lo
#define LAYER_HALVES (8 * 26880 + 3584)
__device__ __align__(16) __nv_bfloat16 g_wimg[5 * LAYER_HALVES];

// ---------------------------------------------------------------------------
// helpers
// ---------------------------------------------------------------------------
__device__ __forceinline__ u32 smem_u32(const void* p) {
    u32 r;
    asm("{ .reg .u64 t; cvta.to.shared.u64 t, %1; cvt.u32.u64 %0, t; }"
        : "=r"(r) : "l"(p));
    return r;
}
__device__ __forceinline__ void cp16(u32 dst, const void* src) {
    asm volatile("cp.async.cg.shared.global [%0], [%1], 16;"
                 :: "r"(dst), "l"(src));
}
__device__ __forceinline__ void cp_commit() { asm volatile("cp.async.commit_group;"); }
template <int N>
__device__ __forceinline__ void cp_waitN() {
    asm volatile("cp.async.wait_group %0;" :: "n"(N));
}

__device__ __forceinline__ void ldsm4(u32* r, u32 addr) {
    asm volatile("ldmatrix.sync.aligned.m8n8.x4.shared.b16 {%0,%1,%2,%3}, [%4];"
        : "=r"(r[0]), "=r"(r[1]), "=r"(r[2]), "=r"(r[3]) : "r"(addr));
}
__device__ __forceinline__ void mma16816(float* c, const u32* a, u32 b0, u32 b1) {
    asm volatile("mma.sync.aligned.m16n8k16.row.col.f32.bf16.bf16.f32 "
        "{%0,%1,%2,%3}, {%4,%5,%6,%7}, {%8,%9}, {%0,%1,%2,%3};"
        : "+f"(c[0]), "+f"(c[1]), "+f"(c[2]), "+f"(c[3])
        : "r"(a[0]), "r"(a[1]), "r"(a[2]), "r"(a[3]), "r"(b0), "r"(b1));
}

// pack/unpack fp32 <-> (bf16 hi in low16 | bf16 lo in high16)
__device__ __forceinline__ u32 pack_hl(float v) {
    __nv_bfloat16 h = __float2bfloat16(v);
    float fh = __bfloat162float(h);
    __nv_bfloat16 l = __float2bfloat16(v - fh);
    return (u32)__bfloat16_as_ushort(h) | ((u32)__bfloat16_as_ushort(l) << 16);
}
__device__ __forceinline__ float unpack_hl(u32 b) {
    return __uint_as_float(b << 16) + __uint_as_float(b & 0xFFFF0000u);
}

// f32x2
__device__ __forceinline__ u64 pack2f(float lo, float hi) {
    u64 r; asm("mov.b64 %0, {%1, %2};" : "=l"(r) : "f"(lo), "f"(hi)); return r;
}
__device__ __forceinline__ void unpack2f(u64 v, float& lo, float& hi) {
    asm("mov.b64 {%0, %1}, %2;" : "=f"(lo), "=f"(hi) : "l"(v));
}
__device__ __forceinline__ void ffma2(u64& acc, u64 a, u64 b) {
    asm("fma.rn.f32x2 %0, %1, %2, %0;" : "+l"(acc) : "l"(a), "l"(b));
}

// ---------------------------------------------------------------------------
// Prep: K-packed weight images. grid = 45 (layer*9 + stage)
// ---------------------------------------------------------------------------
__global__ __launch_bounds__(256) void prep_weights_kernel(
    const float* __restrict__ w_head, const float* __restrict__ w_blocks)
{
    int l = blockIdx.x / 9, s = blockIdx.x - 9 * (blockIdx.x / 9);
    const float* src = (l == 0) ? w_head : (w_blocks + (l - 1) * 90000);
    int stride = (s < 8) ? 120 : 16;
    int nk = (s < 8) ? 112 : 16;
    int splitsz = 112 * stride;
    __nv_bfloat16* dhi = g_wimg + (size_t)l * LAYER_HALVES + s * 26880;
    __nv_bfloat16* dlo = dhi + splitsz;
    int total = 112 * stride;
    for (int i = threadIdx.x; i < total; i += 256) {
        int oc = i / stride, kk = i - stride * (i / stride);
        int k = s * 112 + kk;
        float wv = 0.f;
        if (oc < 100 && kk < nk && k < 900) {
            int kp = k / 100, ci = k - kp * 100;
            wv = src[oc * 900 + ci * 9 + kp];
        }
        __nv_bfloat16 h = __float2bfloat16(wv);
        __nv_bfloat16 lo = __float2bfloat16(wv - __bfloat162float(h));
        dhi[i] = h;
        dlo[i] = lo;
    }
}

// ---------------------------------------------------------------------------
// Kernel 1: warp + concat -> act2_x0 [p][100], smem-buffered coalesced writes
// ---------------------------------------------------------------------------
#define WC_SMEM (256 * 100 * 4)

__global__ __launch_bounds__(256) void warp_concat_kernel(
    const float* __restrict__ f0, const float* __restrict__ f1,
    const float* __restrict__ fd, const float* __restrict__ flow)
{
    extern __shared__ u32 s_out[];   // [256 px][100 ch]
    const int tid = threadIdx.x;
    const int pixbase = blockIdx.x * 256;
    const int p = pixbase + tid;
    u32* row = s_out + tid * 100;

    int y = p / WW, x = p - y * WW;

    #pragma unroll 4
    for (int c = 0; c < 32; c++) row[64 + c] = pack_hl(fd[c * HW + p]);
    #pragma unroll
    for (int c = 0; c < 4; c++)  row[96 + c] = pack_hl(flow[c * HW + p]);

    #pragma unroll
    for (int pair = 0; pair < 2; pair++) {
        const float* img = (pair == 0) ? f0 : f1;
        float px = (float)x + flow[(pair * 2 + 0) * HW + p];
        float py = (float)y + flow[(pair * 2 + 1) * HW + p];
        float fx = floorf(px), fy = floorf(py);
        float wx = px - fx, wy = py - fy;
        int ix = (int)fminf(fmaxf(fx, -2.f), 226.f);
        int iy = (int)fminf(fmaxf(fy, -2.f), 226.f);
        int x0i = min(max(ix, 0), WW - 1);
        int x1i = min(max(ix + 1, 0), WW - 1);
        int y0i = min(max(iy, 0), HH - 1);
        int y1i = min(max(iy + 1, 0), HH - 1);
        float w00 = (1.f - wx) * (1.f - wy);
        float w01 = wx * (1.f - wy);
        float w10 = (1.f - wx) * wy;
        float w11 = wx * wy;
        int b00 = y0i * WW + x0i, b01 = y0i * WW + x1i;
        int b10 = y1i * WW + x0i, b11 = y1i * WW + x1i;
        #pragma unroll 4
        for (int c = 0; c < 32; c++) {
            const float* g = img + c * HW;
            float v = g[b00] * w00 + g[b01] * w01 + g[b10] * w10 + g[b11] * w11;
            row[pair * 32 + c] = pack_hl(v);
        }
    }
    __syncthreads();

    u32* dst = act2_x0 + (size_t)pixbase * 100;
    for (int i = tid; i < 25600; i += 256) dst[i] = s_out[i];
}

// ---------------------------------------------------------------------------
// Kernel 2: HMMA implicit-GEMM 3x3 conv, K-packed (K = 912, 57 ksteps).
// (R15 exact: single-kstep B prefetch, 4-slot ring, distance 2.)
// ---------------------------------------------------------------------------
#define WSTRIDE 240       // smem row stride bytes (full stages)
#define SPLIT_B 26880     // hi->lo offset within full stage
#define SLOT_B  53760     // full stage bytes (ring slot size)
#define CONV_DSMEM (4 * SLOT_B)   // 215040 B
#define TAIL_SPLIT 3584   // hi->lo offset in tail stage

__device__ __forceinline__ void loadB2K(u32* b, int k16, int cib, int kb,
    const u32* rA0, const u32* rA1, bool oA0, bool oA1,
    const u32* rB0, const u32* rB1, bool oB0, bool oB1)
{
    #pragma unroll
    for (int nf = 0; nf < 2; nf++) {
        const u32* rA = nf ? rA1 : rA0; bool oA = nf ? oA1 : oA0;
        const u32* rB = nf ? rB1 : rB0; bool oB = nf ? oB1 : oB0;
        u32 v0 = 0, v1 = 0, w0 = 0, w1 = 0;
        int kv = k16 + cib;
        {
            bool ub = kv >= kb;
            const u32* r = ub ? rB : rA;
            bool ok = ub ? oB : oA;
            int ci = kv - (ub ? kb : kb - 100);
            if (ok) { uint2 t = *(const uint2*)(r + ci); v0 = t.x; v1 = t.y; }
        }
        kv += 8;
        {
            bool ub = kv >= kb;
            const u32* r = ub ? rB : rA;
            bool ok = ub ? oB : oA;
            int ci = kv - (ub ? kb : kb - 100);
            if (ok) { uint2 t = *(const uint2*)(r + ci); w0 = t.x; w1 = t.y; }
        }
        b[nf * 4 + 0] = __byte_perm(v0, v1, 0x5410);  // hi pair k,k+1
        b[nf * 4 + 1] = __byte_perm(w0, w1, 0x5410);  // hi pair k+8,k+9
        b[nf * 4 + 2] = __byte_perm(v0, v1, 0x7632);  // lo pair
        b[nf * 4 + 3] = __byte_perm(w0, w1, 0x7632);
    }
}

template <int MODE>
__global__ __launch_bounds__(256, 1) void conv_hmma_kernel(
    const u32* __restrict__ in,                 // [HW][100]
    const __nv_bfloat16* __restrict__ wimg,     // layer base (halves)
    const float* __restrict__ aux,
    const float* __restrict__ mask,
    u32* __restrict__ outp)                     // [HW][100]
{
    extern __shared__ __align__(16) char dsm[];
    __shared__ float s_mask[128];
    __shared__ float s_aux[112];

    const int tid = threadIdx.x;
    const int w = tid >> 5;
    const int lid = tid & 31;
    const int pixbase = blockIdx.x << 7;

    if (tid < 128) s_mask[tid] = mask[pixbase + tid];
    if (tid < 112) s_aux[tid] = (tid < 100) ? aux[tid] : 0.f;

    const u32 sb = smem_u32(dsm);

    const int p0 = pixbase + w * 16 + (lid >> 2);
    const int p1 = p0 + 8;
    const int py0 = p0 / WW, px0 = p0 - py0 * WW;
    const int py1 = p1 / WW, px1 = p1 - py1 * WW;

    float acc[7][2][4];
    #pragma unroll
    for (int m = 0; m < 7; m++)
        #pragma unroll
        for (int nf = 0; nf < 2; nf++)
            #pragma unroll
            for (int i = 0; i < 4; i++) acc[m][nf][i] = 0.f;

    auto stageW = [&](int s) {
        const char* src = (const char*)wimg + (size_t)s * SLOT_B;
        u32 dst = sb + (s & 3) * SLOT_B;
        int chunks = (s < 8) ? 3360 : 448;
        for (int i = tid; i < chunks; i += 256) cp16(dst + i * 16, src + i * 16);
        cp_commit();
    };

    stageW(0);
    stageW(1);

    const int cib = (lid & 3) * 2;
    const u32 arow = (lid & 15) * WSTRIDE + (lid >> 4) * 16;

    auto rowsFor = [&](int kp, const u32*& r0, const u32*& r1,
                       bool& ok0, bool& ok1) {
        int ky = kp / 3 - 1, kx = kp - 3 * (kp / 3) - 1;
        int iy0 = py0 + ky, ix0 = px0 + kx;
        int iy1 = py1 + ky, ix1 = px1 + kx;
        ok0 = (iy0 >= 0) & (iy0 < HH) & (ix0 >= 0) & (ix0 < WW);
        ok1 = (iy1 >= 0) & (iy1 < HH) & (ix1 >= 0) & (ix1 < WW);
        r0 = in + (size_t)(iy0 * WW + ix0) * 100;
        r1 = in + (size_t)(iy1 * WW + ix1) * 100;
    };

    // A-side = kpos s, B-side = kpos s+1 for stage s
    const u32 *rA0, *rA1, *rB0, *rB1, *rN0, *rN1;
    bool oA0, oA1, oB0, oB1, oN0, oN1;
    rowsFor(0, rA0, rA1, oA0, oA1);
    rowsFor(1, rB0, rB1, oB0, oB1);

    u32 bc[8], bn[8];
    loadB2K(bc, 0, cib, 100, rA0, rA1, oA0, oA1, rB0, rB1, oB0, oB1);

    for (int s = 0; s < 8; s++) {
        if (s + 2 <= 8) stageW(s + 2);
        if (s <= 6) cp_waitN<2>();
        else        cp_waitN<1>();
        __syncthreads();   // single barrier per stage

        const u32 sbuf = sb + (s & 3) * SLOT_B;
        const int kb = (s + 1) * 100;

        if (s < 7) rowsFor(s + 2, rN0, rN1, oN0, oN1);

        #pragma unroll
        for (int ks = 0; ks < 7; ks++) {
            int k16 = s * 112 + ks * 16;
            if (ks < 6) {
                loadB2K(bn, k16 + 16, cib, kb,
                        rA0, rA1, oA0, oA1, rB0, rB1, oB0, oB1);
            } else if (s < 7) {
                loadB2K(bn, 112 * (s + 1), cib, (s + 2) * 100,
                        rB0, rB1, oB0, oB1, rN0, rN1, oN0, oN1);
            } else {  // prefetch tail kstep (k 896..911, kp8 only)
                loadB2K(bn, 896, cib, 900,
                        rB0, rB1, oB0, oB1, rB0, rB1, false, false);
            }

            const u32 kaddr = sbuf + arow + ks * 32;
            #pragma unroll
            for (int m = 0; m < 7; m++) {
                u32 ah[4], al[4];
                ldsm4(ah, kaddr + m * 3840);
                ldsm4(al, kaddr + m * 3840 + SPLIT_B);
                #pragma unroll
                for (int nf = 0; nf < 2; nf++) {
                    mma16816(acc[m][nf], ah, bc[nf * 4 + 0], bc[nf * 4 + 1]); // hh
                    mma16816(acc[m][nf], ah, bc[nf * 4 + 2], bc[nf * 4 + 3]); // h*l
                    mma16816(acc[m][nf], al, bc[nf * 4 + 0], bc[nf * 4 + 1]); // l*h
                }
            }
            #pragma unroll
            for (int q = 0; q < 8; q++) bc[q] = bn[q];
        }
        rA0 = rB0; rA1 = rB1; oA0 = oB0; oA1 = oB1;
        rB0 = rN0; rB1 = rN1; oB0 = oN0; oB1 = oN1;
    }

    // tail stage (s=8, slot 0, 1 kstep, row stride 32 B)
    {
        cp_waitN<0>();
        __syncthreads();
        const u32 sbuf = sb + 0 * SLOT_B;
        const u32 kaddr = sbuf + (lid & 15) * 32 + (lid >> 4) * 16;
        #pragma unroll
        for (int m = 0; m < 7; m++) {
            u32 ah[4], al[4];
            ldsm4(ah, kaddr + m * 512);
            ldsm4(al, kaddr + m * 512 + TAIL_SPLIT);
            #pragma unroll
            for (int nf = 0; nf < 2; nf++) {
                mma16816(acc[m][nf], ah, bc[nf * 4 + 0], bc[nf * 4 + 1]);
                mma16816(acc[m][nf], ah, bc[nf * 4 + 2], bc[nf * 4 + 3]);
                mma16816(acc[m][nf], al, bc[nf * 4 + 0], bc[nf * 4 + 1]);
            }
        }
    }
    __syncthreads();   // protect dsm reuse by epilogue

    // epilogue: transform + smem transpose + coalesced store
    u32* tr = (u32*)dsm;      // [128 px][stride 116] u32
    #pragma unroll
    for (int m = 0; m < 7; m++) {
        const int oc0 = m * 16 + (lid >> 2);
        #pragma unroll
        for (int nf = 0; nf < 2; nf++) {
            const int pxc = w * 16 + nf * 8 + (lid & 3) * 2;
            #pragma unroll
            for (int i = 0; i < 4; i++) {
                const int oc = oc0 + (i >> 1) * 8;
                const int px = pxc + (i & 1);
                if (oc < 100) {
                    float v = acc[m][nf][i];
                    float a = s_aux[oc], mm = s_mask[px];
                    if (MODE == 0) {
                        v = (v >= 0.f ? v : a * v) * mm;
                    } else {
                        v *= mm;
                        v = (v >= 0.f ? v : a * v);
                    }
                    tr[px * 116 + oc] = pack_hl(v);
                }
            }
        }
    }
    __syncthreads();
    for (int i = tid; i < 12800; i += 256) {
        int px = i / 100, ci = i - 100 * (i / 100);
        outp[(size_t)(pixbase + px) * 100 + ci] = tr[px * 116 + ci];
    }
}

// ---------------------------------------------------------------------------
// Kernel 3: 1x1 conv 500 -> 36, f32x2, smem-tiled coalesced reads
// ---------------------------------------------------------------------------
#define C1_SMEM (128 * 101 * 4 + 3600 * 4)

__global__ __launch_bounds__(256) void conv1x1_kernel(
    const u32* __restrict__ feats, const float* __restrict__ wl,
    const float* __restrict__ bl, float* __restrict__ out)
{
    extern __shared__ __align__(16) char c1sm[];
    u32* s_f = (u32*)c1sm;                       // [128 px][101]
    float* s_w = (float*)(c1sm + 128 * 101 * 4);

    const int tid = threadIdx.x;
    const int px = tid & 127;
    const int half = tid >> 7;
    const int prb = half * 9;
    const size_t p = (size_t)blockIdx.x * 128 + px;

    u64 acc[9];
    #pragma unroll
    for (int pr = 0; pr < 9; pr++)
        acc[pr] = pack2f(bl[(prb + pr) * 2], bl[(prb + pr) * 2 + 1]);

    for (int ch = 0; ch < 5; ch++) {
        __syncthreads();
        for (int i = tid; i < 3600; i += 256) {
            int ci = i / 36, o = i - ci * 36;
            s_w[(ci * 18 + (o >> 1)) * 2 + (o & 1)] = wl[o * 500 + ch * 100 + ci];
        }
        const u32* src = feats + ((size_t)ch * HW + (size_t)blockIdx.x * 128) * 100;
        for (int i = tid; i < 12800; i += 256) {
            int lpx = i / 100, lci = i - 100 * (i / 100);
            s_f[lpx * 101 + lci] = src[i];
        }
        __syncthreads();

        const u32* fp = s_f + px * 101;
        #pragma unroll 4
        for (int ci = 0; ci < 100; ci++) {
            float f = unpack_hl(fp[ci]);
            u64 f2 = pack2f(f, f);
            const u64* wp = (const u64*)(s_w + ci * 36) + prb;
            #pragma unroll
            for (int pr = 0; pr < 9; pr++) ffma2(acc[pr], wp[pr], f2);
        }
    }
    #pragma unroll
    for (int pr = 0; pr < 9; pr++) {
        float v0, v1;
        unpack2f(acc[pr], v0, v1);
        out[((prb + pr) * 2 + 0) * HW + p] = v0;
        out[((prb + pr) * 2 + 1) * HW + p] = v1;
    }
}

// ---------------------------------------------------------------------------
// Kernel 2b: small 3x3 conv (mask head), 32 -> 2, bias.
// Single-stage: all 32 channels' halo tiles + weights staged once, ONE
// barrier, then straight FMA. Tile 32x16, 512 threads.
// ---------------------------------------------------------------------------
__global__ __launch_bounds__(512) void conv3x3_small_kernel(
    const float* __restrict__ in, const float* __restrict__ wgt,
    const float* __restrict__ bias, float* __restrict__ out)
{
    __shared__ float s_in[32 * 18 * 34];   // 32 ch x 18 rows x 34 cols = 78336 B
    __shared__ float s_w[2 * 32 * 9];

    const int tid = threadIdx.x;
    const int tx = tid & 31;
    const int ty = tid >> 5;               // 0..15
    const int ox0 = blockIdx.x * 32;
    const int oy0 = blockIdx.y * 16;
    const int ox = ox0 + tx, oy = oy0 + ty;

    // stage inputs: 32 ch x 18 x 34
    for (int idx = tid; idx < 32 * 18 * 34; idx += 512) {
        int ci = idx / 612;
        int rem = idx - ci * 612;
        int r = rem / 34, c = rem - r * 34;
        int gy = oy0 - 1 + r, gx = ox0 - 1 + c;
        float v = 0.f;
        if (gx >= 0 && gx < WW && gy >= 0 && gy < HH)
            v = in[ci * HW + gy * WW + gx];
        s_in[idx] = v;
    }
    // stage weights [2 oc][32 ci][9]
    for (int i = tid; i < 576; i += 512) s_w[i] = wgt[i];
    __syncthreads();

    float acc0 = bias[0], acc1 = bias[1];
    #pragma unroll 4
    for (int ci = 0; ci < 32; ci++) {
        const float* si = s_in + ci * 612 + ty * 34 + tx;
        const float* w0 = s_w + ci * 9;
        const float* w1 = s_w + 288 + ci * 9;
        #pragma unroll
        for (int ky = 0; ky < 3; ky++)
            #pragma unroll
            for (int kx = 0; kx < 3; kx++) {
                float v = si[ky * 34 + kx];
                acc0 = fmaf(w0[ky * 3 + kx], v, acc0);
                acc1 = fmaf(w1[ky * 3 + kx], v, acc1);
            }
    }
    out[oy * WW + ox] = acc0;
    out[HW + oy * WW + ox] = acc1;
}

// ---------------------------------------------------------------------------
// Kernel 4: 2x bilinear upsample + mask
// ---------------------------------------------------------------------------
__global__ __launch_bounds__(256) void upsample_kernel(
    const float* __restrict__ x36, const float* __restrict__ smn,
    const float* __restrict__ smask, float* __restrict__ out)
{
    int p = blockIdx.x * 256 + threadIdx.x;
    if (p >= OHW) return;
    int oy = p / OW, ox = p - oy * OW;
    int iy = oy >> 1, ix = ox >> 1;

    int r0, r1; float wr0, wr1;
    if (oy & 1) { r0 = iy; r1 = min(iy + 1, HH - 1); wr0 = 0.75f; wr1 = 0.25f; }
    else        { r0 = max(iy - 1, 0); r1 = iy;      wr0 = 0.25f; wr1 = 0.75f; }
    int c0, c1; float wc0, wc1;
    if (ox & 1) { c0 = ix; c1 = min(ix + 1, WW - 1); wc0 = 0.75f; wc1 = 0.25f; }
    else        { c0 = max(ix - 1, 0); c1 = ix;      wc0 = 0.25f; wc1 = 0.75f; }

    int b00 = r0 * WW + c0, b01 = r0 * WW + c1;
    int b10 = r1 * WW + c0, b11 = r1 * WW + c1;

    #pragma unroll 4
    for (int ch = 0; ch < 36; ch++) {
        const float* g = x36 + ch * HW;
        float v = wr0 * (wc0 * g[b00] + wc1 * g[b01]) +
                  wr1 * (wc0 * g[b10] + wc1 * g[b11]);
        out[ch * OHW + p] = v;
    }

    const float* s0p = smn;
    const float* s1p = smn + HW;
    float s0 = wr0 * (wc0 * s0p[b00] + wc1 * s0p[b01]) +
               wr1 * (wc0 * s0p[b10] + wc1 * s0p[b11]);
    float s1 = wr0 * (wc0 * s1p[b00] + wc1 * s1p[b01]) +
               wr1 * (wc0 * s1p[b10] + wc1 * s1p[b11]);
    float mu = smask[iy * WW + ix];
    out[36 * OHW + p] = (s0 > s1) ? mu : 0.f;
}

// ---------------------------------------------------------------------------
// Launcher
// ---------------------------------------------------------------------------
extern "C" void kernel_launch(void* const* d_in, const int* in_sizes, int n_in,
                              void* d_out, int out_size)
{
    const float* feat_0     = (const float*)d_in[0];
    const float* feat_1     = (const float*)d_in[1];
    const float* feat_dense = (const float*)d_in[2];
    const float* flow       = (const float*)d_in[3];
    const float* space_mask = (const float*)d_in[4];
    const float* w_head     = (const float*)d_in[5];
    const float* a_head     = (const float*)d_in[6];
    const float* w_blocks   = (const float*)d_in[7];
    const float* a_blocks   = (const float*)d_in[8];
    const float* w_last     = (const float*)d_in[9];
    const float* b_last     = (const float*)d_in[10];
    const float* w_mask     = (const float*)d_in[11];
    const float* b_mask     = (const float*)d_in[12];

    u32 *x0a, *featsa;
    float *x36, *smn;
    __nv_bfloat16* wimg;
    cudaGetSymbolAddress((void**)&x0a,    act2_x0);
    cudaGetSymbolAddress((void**)&featsa, act2_feats);
    cudaGetSymbolAddress((void**)&x36,    g_x36);
    cudaGetSymbolAddress((void**)&smn,    g_smn);
    cudaGetSymbolAddress((void**)&wimg,   g_wimg);

    cudaFuncSetAttribute(conv_hmma_kernel<0>,
                         cudaFuncAttributeMaxDynamicSharedMemorySize, CONV_DSMEM);
    cudaFuncSetAttribute(conv_hmma_kernel<1>,
                         cudaFuncAttributeMaxDynamicSharedMemorySize, CONV_DSMEM);
    cudaFuncSetAttribute(warp_concat_kernel,
                         cudaFuncAttributeMaxDynamicSharedMemorySize, WC_SMEM);
    cudaFuncSetAttribute(conv1x1_kernel,
                         cudaFuncAttributeMaxDynamicSharedMemorySize, C1_SMEM);

    prep_weights_kernel<<<45, 256>>>(w_head, w_blocks);
    warp_concat_kernel<<<196, 256, WC_SMEM>>>(feat_0, feat_1, feat_dense, flow);

    conv_hmma_kernel<0><<<392, 256, CONV_DSMEM>>>(
        x0a, wimg, a_head, space_mask, featsa);
    for (int i = 1; i < 5; i++) {
        conv_hmma_kernel<1><<<392, 256, CONV_DSMEM>>>(
            featsa + (size_t)(i - 1) * HW * 100,
            wimg + (size_t)i * LAYER_HALVES,
            a_blocks + (i - 1) * 100,
            space_mask,
            featsa + (size_t)i * HW * 100);
    }

    conv1x1_kernel<<<392, 256, C1_SMEM>>>(featsa, w_last, b_last, x36);

    conv3x3_small_kernel<<<dim3(7, 14, 1), 512>>>(
        x36 + 4 * HW, w_mask, b_mask, smn);

    upsample_kernel<<<784, 256>>>(x36, smn, space_mask, (float*)d_out);
}